// round 1
// baseline (speedup 1.0000x reference)
#include <cuda_runtime.h>

// Problem constants
// x        : [N, I]    float32   (N = 4096, I = 512)
// var      : [N, D]    float32   (D = 64)
// W        : [D, I, O] float32   == row-major [D*I, O] = B matrix [32768, 512]
// b1       : [D, O]    float32   == 64 extra K rows with A = var
// out      : [N, O]    float32
//
// out = A @ B where A[n, d*I+i] = var[n,d]*x[n,i], A[n, D*I+d] = var[n,d]
//                   B = concat(W.reshape(D*I, O), b1)

#define DD 64
#define II 512
#define OO 512

#define BM 128
#define BN 64
#define BK 16
#define TM 8
#define TN 4
#define NTHREADS 256   // (BM/TM)*(BN/TN) = 16*16

__global__ __launch_bounds__(NTHREADS) void fused_mlp_kernel(
    const float* __restrict__ x,
    const float* __restrict__ var,
    const float* __restrict__ W,
    const float* __restrict__ b1,
    float* __restrict__ out)
{
    __shared__ float As[BK][BM];       // A tile, transposed (k-major)
    __shared__ float Bs[BK][BN];       // B tile
    __shared__ float Vs[BM][DD + 1];   // var rows for this block (padded vs bank conflicts)

    const int tid     = threadIdx.x;
    const int rowBase = blockIdx.y * BM;
    const int colBase = blockIdx.x * BN;

    // Stage this block's var rows: 128*64 = 8192 floats, 32 per thread.
    for (int idx = tid; idx < BM * DD; idx += NTHREADS) {
        int m = idx >> 6;
        int d = idx & 63;
        Vs[m][d] = var[(rowBase + m) * DD + d];
    }
    __syncthreads();

    float acc[TM][TN];
#pragma unroll
    for (int i = 0; i < TM; ++i)
#pragma unroll
        for (int j = 0; j < TN; ++j) acc[i][j] = 0.0f;

    // Compute-thread coordinates
    const int ty = tid >> 4;        // 0..15 -> rows ty*8 .. ty*8+7
    const int tx = tid & 15;        // 0..15 -> cols tx*4 .. tx*4+3

    // A-loader coordinates: 2 threads per row, each loads 8 consecutive k
    const int lm = tid >> 1;        // row within tile: 0..127
    const int lh = (tid & 1) * 8;   // kk offset: 0 or 8

    // B-loader coordinates: 16 threads per k-row, each loads float4
    const int bk = tid >> 4;        // 0..15
    const int bo = (tid & 15) * 4;  // 0..60

    const int KT_MAIN = (DD * II) / BK;   // 2048 tiles over W

    for (int kt = 0; kt < KT_MAIN; ++kt) {
        const int k0 = kt * BK;
        const int d  = k0 >> 9;           // fixed per tile (512/16 = 32 tiles per d)
        const int i0 = k0 & (II - 1);

        // ---- load A tile: x * var ----
        {
            const float v = Vs[lm][d];
            const float4* xp =
                reinterpret_cast<const float4*>(&x[(size_t)(rowBase + lm) * II + i0 + lh]);
            float4 a0 = xp[0];
            float4 a1 = xp[1];
            As[lh + 0][lm] = a0.x * v;
            As[lh + 1][lm] = a0.y * v;
            As[lh + 2][lm] = a0.z * v;
            As[lh + 3][lm] = a0.w * v;
            As[lh + 4][lm] = a1.x * v;
            As[lh + 5][lm] = a1.y * v;
            As[lh + 6][lm] = a1.z * v;
            As[lh + 7][lm] = a1.w * v;
        }
        // ---- load B tile: W rows ----
        {
            float4 bvec = *reinterpret_cast<const float4*>(
                &W[(size_t)(k0 + bk) * OO + colBase + bo]);
            *reinterpret_cast<float4*>(&Bs[bk][bo]) = bvec;
        }
        __syncthreads();

        // ---- compute ----
#pragma unroll
        for (int kk = 0; kk < BK; ++kk) {
            const float4* ap = reinterpret_cast<const float4*>(&As[kk][ty * TM]);
            float4 a0 = ap[0];
            float4 a1 = ap[1];
            float4 bf = *reinterpret_cast<const float4*>(&Bs[kk][tx * TN]);
            float af[TM] = {a0.x, a0.y, a0.z, a0.w, a1.x, a1.y, a1.z, a1.w};
            float bb[TN] = {bf.x, bf.y, bf.z, bf.w};
#pragma unroll
            for (int i = 0; i < TM; ++i)
#pragma unroll
                for (int j = 0; j < TN; ++j)
                    acc[i][j] = fmaf(af[i], bb[j], acc[i][j]);
        }
        __syncthreads();
    }

    // ---- bias tiles: 4 tiles of BK=16 over d, A = var, B = b1 ----
#pragma unroll
    for (int dt = 0; dt < DD / BK; ++dt) {
#pragma unroll
        for (int j = 0; j < 8; ++j)
            As[lh + j][lm] = Vs[lm][dt * BK + lh + j];
        {
            float4 bvec = *reinterpret_cast<const float4*>(
                &b1[(size_t)(dt * BK + bk) * OO + colBase + bo]);
            *reinterpret_cast<float4*>(&Bs[bk][bo]) = bvec;
        }
        __syncthreads();
#pragma unroll
        for (int kk = 0; kk < BK; ++kk) {
            const float4* ap = reinterpret_cast<const float4*>(&As[kk][ty * TM]);
            float4 a0 = ap[0];
            float4 a1 = ap[1];
            float4 bf = *reinterpret_cast<const float4*>(&Bs[kk][tx * TN]);
            float af[TM] = {a0.x, a0.y, a0.z, a0.w, a1.x, a1.y, a1.z, a1.w};
            float bb[TN] = {bf.x, bf.y, bf.z, bf.w};
#pragma unroll
            for (int i = 0; i < TM; ++i)
#pragma unroll
                for (int j = 0; j < TN; ++j)
                    acc[i][j] = fmaf(af[i], bb[j], acc[i][j]);
        }
        __syncthreads();
    }

    // ---- epilogue: vectorized stores ----
#pragma unroll
    for (int i = 0; i < TM; ++i) {
        float4 o4;
        o4.x = acc[i][0];
        o4.y = acc[i][1];
        o4.z = acc[i][2];
        o4.w = acc[i][3];
        *reinterpret_cast<float4*>(
            &out[(size_t)(rowBase + ty * TM + i) * OO + colBase + tx * TN]) = o4;
    }
}

extern "C" void kernel_launch(void* const* d_in, const int* in_sizes, int n_in,
                              void* d_out, int out_size) {
    const float* x   = (const float*)d_in[0];   // [N, 512]
    const float* var = (const float*)d_in[1];   // [N, 64]
    const float* W   = (const float*)d_in[2];   // [64, 512, 512]
    const float* b1  = (const float*)d_in[3];   // [64, 512]
    float* out       = (float*)d_out;           // [N, 512]

    const int N = in_sizes[1] / DD;             // 4096

    dim3 grid(OO / BN, N / BM);                 // (8, 32) = 256 blocks
    fused_mlp_kernel<<<grid, NTHREADS>>>(x, var, W, b1, out);
}

// round 4
// speedup vs baseline: 1.9947x; 1.9947x over previous
#include <cuda_runtime.h>
#include <cstdint>
#include <cstddef>

#define NROWS 4096
#define ODIM  512
#define IDIM  512
#define DDIM  64

#define BM 128
#define BN 64
#define NTH 256
#define NTILES 513         // 512 W tiles (i) + 1 bias tile

#define A_STAGE 32768u     // 128 rows x 256B
#define B_OFF   65536u
#define B_STAGE 17408u     // 64 rows x 272B (68-float padded rows)
#define SMEM_TOTAL (65536 + 3 * 17408)

__device__ float g_xT[IDIM * NROWS];   // x transposed: [512][4096]

// ---------------- helpers ----------------
__device__ __forceinline__ uint32_t smem_u32(const void* p) {
    uint32_t a;
    asm("{ .reg .u64 t; cvta.to.shared.u64 t, %1; cvt.u32.u64 %0, t; }" : "=r"(a) : "l"(p));
    return a;
}
__device__ __forceinline__ uint32_t f2tf32(float f) {
    uint32_t r;
    asm("cvt.rna.tf32.f32 %0, %1;" : "=r"(r) : "f"(f));
    return r;
}
#define CP_ASYNC16(dst, src) \
    asm volatile("cp.async.cg.shared.global [%0], [%1], 16;" :: "r"(dst), "l"(src) : "memory")
#define CP_COMMIT() asm volatile("cp.async.commit_group;" ::: "memory")
#define CP_WAIT2()  asm volatile("cp.async.wait_group 2;" ::: "memory")

#define STS64V(a, lo, hi) \
    asm volatile("st.shared.v2.b32 [%0], {%1, %2};" :: "r"(a), "r"(lo), "r"(hi) : "memory")
#define LDS64V(lo, hi, a) \
    asm volatile("ld.shared.v2.b32 {%0, %1}, [%2];" : "=r"(lo), "=r"(hi) : "r"(a))
#define LDS32(v, a) \
    asm volatile("ld.shared.b32 %0, [%1];" : "=r"(v) : "r"(a))

__device__ __forceinline__ void mma_tf32_16x8x8(float& c0, float& c1, float& c2, float& c3,
                                                uint32_t a0, uint32_t a1, uint32_t a2, uint32_t a3,
                                                uint32_t b0, uint32_t b1) {
    asm volatile(
        "mma.sync.aligned.m16n8k8.row.col.f32.tf32.tf32.f32 "
        "{%0,%1,%2,%3}, {%4,%5,%6,%7}, {%8,%9}, {%0,%1,%2,%3};"
        : "+f"(c0), "+f"(c1), "+f"(c2), "+f"(c3)
        : "r"(a0), "r"(a1), "r"(a2), "r"(a3), "r"(b0), "r"(b1));
}

// ---------------- x transpose ----------------
__global__ void __launch_bounds__(1024) transpose_x(const float* __restrict__ x) {
    __shared__ float t[32][33];
    const int bi = blockIdx.x * 32;
    const int bn = blockIdx.y * 32;
    t[threadIdx.y][threadIdx.x] = x[(size_t)(bn + threadIdx.y) * IDIM + bi + threadIdx.x];
    __syncthreads();
    g_xT[(size_t)(bi + threadIdx.y) * NROWS + bn + threadIdx.x] = t[threadIdx.x][threadIdx.y];
}

// ---------------- main mma.sync kernel ----------------
__global__ void __launch_bounds__(NTH, 1) mlp_mma(
    const float* __restrict__ var,
    const float* __restrict__ W,
    const float* __restrict__ b1,
    float* __restrict__ out)
{
    extern __shared__ __align__(128) uint8_t smem[];
    const uint32_t s0 = smem_u32(smem);

    const int tid  = threadIdx.x;
    const int lane = tid & 31;
    const int w    = tid >> 5;
    const int rowBase = blockIdx.y * BM;
    const int colBase = blockIdx.x * BN;

    // ----- producer-role constants (A tile) -----
    const int pm = tid & 127;          // row owned
    const int ph = tid >> 7;           // d half: 0 -> d 0..31, 1 -> d 32..63
    float vr[32];
    {
        const float4* vp = reinterpret_cast<const float4*>(
            var + (size_t)(rowBase + pm) * DDIM + ph * 32);
#pragma unroll
        for (int q = 0; q < 8; ++q) {
            float4 v = vp[q];
            vr[q * 4 + 0] = v.x; vr[q * 4 + 1] = v.y;
            vr[q * 4 + 2] = v.z; vr[q * 4 + 3] = v.w;
        }
    }
    const uint32_t aProd = s0 + (uint32_t)pm * 256u;
    const uint32_t mxor  = (uint32_t)(pm & 7);

    // ----- producer-role constants (B tile via cp.async) -----
    // physical row p = tid/4; logical j from q=p&7: j = (q>>1) + 4*(q&1); d = (p&~7)+j
    const int bp = tid >> 2;
    const int bq = bp & 7;
    const int bd = (bp & ~7) + ((bq >> 1) + ((bq & 1) << 2));
    const int bc = (tid & 3) * 16;     // float offset (64B sub-block)
    const uint32_t bDst0 = s0 + B_OFF + (uint32_t)bp * 272u + (uint32_t)(tid & 3) * 64u;
    const float* bSrcW = W + (size_t)bd * IDIM * ODIM + colBase + bc;   // + t*ODIM
    const float* bSrcB = b1 + (size_t)bd * ODIM + colBase + bc;

    // ----- consumer-role constants -----
    const int wm = (w & 3) * 32;       // warp m-base
    const int wn = (w >> 2) * 32;      // warp n-base
    const uint32_t aXor = (uint32_t)(lane >> 2);   // = m & 7 for all frag rows
    uint32_t aRowAddr[2][2];
#pragma unroll
    for (int mt = 0; mt < 2; ++mt)
#pragma unroll
        for (int hf = 0; hf < 2; ++hf)
            aRowAddr[mt][hf] = (uint32_t)(wm + mt * 16 + hf * 8 + (lane >> 2)) * 256u
                               + (uint32_t)(lane & 3) * 8u;
    const uint32_t bRow0   = (uint32_t)(lane & 3) * 2u;          // physical row pair
    const uint32_t bColOff = (uint32_t)(wn + (lane >> 2)) * 4u;  // + nt*32

    float C[2][4][4];
#pragma unroll
    for (int mt = 0; mt < 2; ++mt)
#pragma unroll
        for (int nt = 0; nt < 4; ++nt)
#pragma unroll
            for (int q = 0; q < 4; ++q) C[mt][nt][q] = 0.0f;

    // ----- helpers as lambdas -----
    auto issueB = [&](int t, int s) {
        const float* src = (t < 512) ? (bSrcW + (size_t)t * ODIM) : bSrcB;
        uint32_t dst = bDst0 + (uint32_t)s * B_STAGE;
#pragma unroll
        for (int c = 0; c < 4; ++c)
            CP_ASYNC16(dst + (uint32_t)c * 16u, src + c * 4);
    };
    auto produceA = [&](int t, int b) {
        float xv = 1.0f;
        if (t < 512) xv = __ldg(&g_xT[(size_t)t * NROWS + rowBase + pm]);
        const uint32_t ab = aProd + (uint32_t)b * A_STAGE;
#pragma unroll
        for (int g = 0; g < 4; ++g) {
            const uint32_t G   = (uint32_t)(ph * 4 + g);
            const uint32_t blk = (G ^ mxor) << 5;
#pragma unroll
            for (int j = 0; j < 4; ++j) {
                uint32_t lo = f2tf32(xv * vr[g * 8 + j]);
                uint32_t hi = f2tf32(xv * vr[g * 8 + j + 4]);
                STS64V(ab + blk + (uint32_t)j * 8u, lo, hi);
            }
        }
    };

    // ----- prologue: 3 B stages in flight, A(0) produced -----
    issueB(0, 0); CP_COMMIT();
    issueB(1, 1); CP_COMMIT();
    issueB(2, 2); CP_COMMIT();
    produceA(0, 0);

    // ----- mainloop -----
    for (int i = 0; i < NTILES; ++i) {
        CP_WAIT2();            // B(i) landed (≤2 younger groups pending)
        __syncthreads();       // B(i) + A(i) visible to all

        if (i + 1 <= 512) produceA(i + 1, (i + 1) & 1);

        const uint32_t aB = s0 + (uint32_t)(i & 1) * A_STAGE;
        const uint32_t bB = s0 + B_OFF + (uint32_t)(i % 3) * B_STAGE;

#pragma unroll
        for (int ks = 0; ks < 8; ++ks) {
            const uint32_t aOff = aB + (((uint32_t)ks ^ aXor) << 5);
            uint32_t a[2][4];
#pragma unroll
            for (int mt = 0; mt < 2; ++mt) {
                LDS64V(a[mt][0], a[mt][2], aOff + aRowAddr[mt][0]);
                LDS64V(a[mt][1], a[mt][3], aOff + aRowAddr[mt][1]);
            }
            const uint32_t bRow = bB + ((uint32_t)ks * 8u + bRow0) * 272u + bColOff;
            uint32_t b[4][2];
#pragma unroll
            for (int nt = 0; nt < 4; ++nt) {
                LDS32(b[nt][0], bRow + (uint32_t)nt * 32u);
                LDS32(b[nt][1], bRow + (uint32_t)nt * 32u + 272u);
            }
#pragma unroll
            for (int mt = 0; mt < 2; ++mt)
#pragma unroll
                for (int nt = 0; nt < 4; ++nt)
                    mma_tf32_16x8x8(C[mt][nt][0], C[mt][nt][1], C[mt][nt][2], C[mt][nt][3],
                                    a[mt][0], a[mt][1], a[mt][2], a[mt][3],
                                    b[nt][0], b[nt][1]);
        }

        __syncthreads();       // all done reading B stage i%3 before refill
        if (i + 3 <= 512) issueB(i + 3, (i + 3) % 3);
        CP_COMMIT();
    }

    // ----- epilogue: compensate tf32 RZ-truncation of B with (1 + 2^-11) -----
    const float SCL = 1.00048828125f;
#pragma unroll
    for (int mt = 0; mt < 2; ++mt) {
        const int r0 = rowBase + wm + mt * 16 + (lane >> 2);
#pragma unroll
        for (int nt = 0; nt < 4; ++nt) {
            const int c0 = colBase + wn + nt * 8 + (lane & 3) * 2;
            float2 v0, v1;
            v0.x = C[mt][nt][0] * SCL; v0.y = C[mt][nt][1] * SCL;
            v1.x = C[mt][nt][2] * SCL; v1.y = C[mt][nt][3] * SCL;
            *reinterpret_cast<float2*>(&out[(size_t)r0 * ODIM + c0]) = v0;
            *reinterpret_cast<float2*>(&out[(size_t)(r0 + 8) * ODIM + c0]) = v1;
        }
    }
}

// ---------------- host ----------------
extern "C" void kernel_launch(void* const* d_in, const int* in_sizes, int n_in,
                              void* d_out, int out_size) {
    const float* x   = (const float*)d_in[0];   // [4096, 512]
    const float* var = (const float*)d_in[1];   // [4096, 64]
    const float* W   = (const float*)d_in[2];   // [64, 512, 512]
    const float* b1  = (const float*)d_in[3];   // [64, 512]
    float* out       = (float*)d_out;           // [4096, 512]

    {
        dim3 tb(32, 32), tg(IDIM / 32, NROWS / 32);
        transpose_x<<<tg, tb>>>(x);
    }

    cudaFuncSetAttribute(mlp_mma, cudaFuncAttributeMaxDynamicSharedMemorySize, SMEM_TOTAL);
    dim3 grid(ODIM / BN, NROWS / BM);   // (8, 32) = 256 CTAs
    mlp_mma<<<grid, NTH, SMEM_TOTAL>>>(var, W, b1, out);
}

// round 5
// speedup vs baseline: 3.0382x; 1.5231x over previous
#include <cuda_runtime.h>
#include <cstdint>
#include <cstddef>

#define NROWS 4096
#define ODIM  512
#define IDIM  512
#define DDIM  64

#define BM 128
#define BN 128
#define NTH 256
#define NTILES 513            // 512 W tiles (i) + 1 bias tile

#define BPITCH 544u           // bytes per d-row: 128 floats + 8 pad (8c+o' -> conflict-free)
#define B_STAGE (64u * BPITCH)       // 34816 B
#define NSTAGE 4
#define SMEM_TOTAL (4 * 34816)       // 139264 B

__device__ float g_xT[IDIM * NROWS];   // x transposed: [512][4096]

// ---------------- helpers ----------------
__device__ __forceinline__ uint32_t smem_u32(const void* p) {
    uint32_t a;
    asm("{ .reg .u64 t; cvta.to.shared.u64 t, %1; cvt.u32.u64 %0, t; }" : "=r"(a) : "l"(p));
    return a;
}
__device__ __forceinline__ uint32_t f2tf32(float f) {
    uint32_t r;
    asm("cvt.rna.tf32.f32 %0, %1;" : "=r"(r) : "f"(f));
    return r;
}
#define CP_ASYNC16(dst, src) \
    asm volatile("cp.async.cg.shared.global [%0], [%1], 16;" :: "r"(dst), "l"(src) : "memory")
#define CP_COMMIT() asm volatile("cp.async.commit_group;" ::: "memory")
#define CP_WAIT2()  asm volatile("cp.async.wait_group 2;" ::: "memory")

#define LDS32(v, a) asm volatile("ld.shared.b32 %0, [%1];" : "=r"(v) : "r"(a))

__device__ __forceinline__ void mma_tf32_16x8x8(float& c0, float& c1, float& c2, float& c3,
                                                uint32_t a0, uint32_t a1, uint32_t a2, uint32_t a3,
                                                uint32_t b0, uint32_t b1) {
    asm volatile(
        "mma.sync.aligned.m16n8k8.row.col.f32.tf32.tf32.f32 "
        "{%0,%1,%2,%3}, {%4,%5,%6,%7}, {%8,%9}, {%0,%1,%2,%3};"
        : "+f"(c0), "+f"(c1), "+f"(c2), "+f"(c3)
        : "r"(a0), "r"(a1), "r"(a2), "r"(a3), "r"(b0), "r"(b1));
}

// ---------------- x transpose ----------------
__global__ void __launch_bounds__(1024) transpose_x(const float* __restrict__ x) {
    __shared__ float t[32][33];
    const int bi = blockIdx.x * 32;
    const int bn = blockIdx.y * 32;
    t[threadIdx.y][threadIdx.x] = x[(size_t)(bn + threadIdx.y) * IDIM + bi + threadIdx.x];
    __syncthreads();
    g_xT[(size_t)(bi + threadIdx.y) * NROWS + bn + threadIdx.x] = t[threadIdx.x][threadIdx.y];
}

// ---------------- main kernel: register-direct A fragments ----------------
__global__ void __launch_bounds__(NTH, 1) mlp_mma(
    const float* __restrict__ var,
    const float* __restrict__ W,
    const float* __restrict__ b1,
    float* __restrict__ out)
{
    extern __shared__ __align__(128) uint8_t smem[];
    const uint32_t s0 = smem_u32(smem);

    const int tid  = threadIdx.x;
    const int lane = tid & 31;
    const int w    = tid >> 5;
    const int rowBase = blockIdx.y * BM;
    const int colBase = blockIdx.x * BN;

    const int wm = (w & 3) * 32;    // warp m-base within CTA (4 warps over M)
    const int wn = (w >> 2) * 64;   // warp n-base within CTA (2 warps over N)
    const int c  = lane & 3;        // k-index within quad
    const int og = lane >> 2;       // o-group / row-group

    // ----- this thread's 4 fragment rows (fixed for the whole kernel) -----
    // rr = mt*2 + half: rows rowBase + wm + mt*16 + half*8 + og
    int xr[4];
#pragma unroll
    for (int rr = 0; rr < 4; ++rr)
        xr[rr] = rowBase + wm + (rr >> 1) * 16 + (rr & 1) * 8 + og;

    // ----- var values in registers: v[rr][t], d = c + 4t, t = 0..15 -----
    float v[4][16];
#pragma unroll
    for (int rr = 0; rr < 4; ++rr)
#pragma unroll
        for (int t16 = 0; t16 < 16; ++t16)
            v[rr][t16] = __ldg(&var[(size_t)xr[rr] * DDIM + c + 4 * t16]);

    // ----- B loader constants (cp.async), natural d order -----
    const int brow = tid >> 2;                 // d row: 0..63
    const int bco  = (tid & 3) * 32;           // float offset (this thread's 128B chunk)
    const uint32_t bDst = s0 + (uint32_t)brow * BPITCH + (uint32_t)(tid & 3) * 128u;
    const float* bW = W + (size_t)brow * IDIM * ODIM + colBase + bco;   // + t*ODIM
    const float* bB = b1 + (size_t)brow * ODIM + colBase + bco;

    auto issueB = [&](int t) {
        const float* src = (t < 512) ? (bW + (size_t)t * ODIM) : bB;
        const uint32_t d = bDst + (uint32_t)(t & 3) * B_STAGE;
#pragma unroll
        for (int c8 = 0; c8 < 8; ++c8)
            CP_ASYNC16(d + (uint32_t)c8 * 16u, src + c8 * 4);
        CP_COMMIT();
    };

    auto loadX = [&](int t, float* dst) {
        if (t < 512) {
#pragma unroll
            for (int rr = 0; rr < 4; ++rr)
                dst[rr] = __ldg(&g_xT[(size_t)t * NROWS + xr[rr]]);
        } else {
#pragma unroll
            for (int rr = 0; rr < 4; ++rr) dst[rr] = 1.0f;
        }
    };

    float C[2][8][4];
#pragma unroll
    for (int mt = 0; mt < 2; ++mt)
#pragma unroll
        for (int nt = 0; nt < 8; ++nt)
#pragma unroll
            for (int q = 0; q < 4; ++q) C[mt][nt][q] = 0.0f;

    // ----- prologue: 3 B stages in flight, x(0) loaded -----
    issueB(0); issueB(1); issueB(2);
    float xc[4], xn[4];
    loadX(0, xc);

    // ----- mainloop: one __syncthreads per tile -----
    const uint32_t bColOff = (uint32_t)(wn + og) * 4u;
    for (int i = 0; i < NTILES; ++i) {
        CP_WAIT2();            // B(i) landed (≤2 younger groups pending)
        __syncthreads();       // all threads done reading stage (i-1)%4

        if (i + 3 <= 512) issueB(i + 3);   // writes stage (i+3)%4 == (i-1)%4: safe after sync
        loadX(i + 1, xn);                  // prefetch next tile's x scalars

        const uint32_t bB0 = s0 + (uint32_t)(i & 3) * B_STAGE;

#pragma unroll
        for (int ks = 0; ks < 8; ++ks) {
            // B fragments: b0 at d-row 8ks+c, b1 at 8ks+c+4 (conflict-free: 8c+o')
            const uint32_t rAddr = bB0 + (uint32_t)(8 * ks + c) * BPITCH + bColOff;
            uint32_t b[8][2];
#pragma unroll
            for (int nt = 0; nt < 8; ++nt) {
                LDS32(b[nt][0], rAddr + (uint32_t)nt * 32u);
                LDS32(b[nt][1], rAddr + 4u * BPITCH + (uint32_t)nt * 32u);
            }
            // A fragments: register-direct, d = 8ks + c (+4)  ->  t = 2ks (+1)
            uint32_t a[2][4];
#pragma unroll
            for (int mt = 0; mt < 2; ++mt) {
                a[mt][0] = f2tf32(xc[mt * 2 + 0] * v[mt * 2 + 0][2 * ks]);
                a[mt][1] = f2tf32(xc[mt * 2 + 1] * v[mt * 2 + 1][2 * ks]);
                a[mt][2] = f2tf32(xc[mt * 2 + 0] * v[mt * 2 + 0][2 * ks + 1]);
                a[mt][3] = f2tf32(xc[mt * 2 + 1] * v[mt * 2 + 1][2 * ks + 1]);
            }
#pragma unroll
            for (int mt = 0; mt < 2; ++mt)
#pragma unroll
                for (int nt = 0; nt < 8; ++nt)
                    mma_tf32_16x8x8(C[mt][nt][0], C[mt][nt][1], C[mt][nt][2], C[mt][nt][3],
                                    a[mt][0], a[mt][1], a[mt][2], a[mt][3],
                                    b[nt][0], b[nt][1]);
        }

#pragma unroll
        for (int rr = 0; rr < 4; ++rr) xc[rr] = xn[rr];
    }

    // ----- epilogue: compensate tf32 RZ-truncation of B with (1 + 2^-11) -----
    const float SCL = 1.00048828125f;
#pragma unroll
    for (int mt = 0; mt < 2; ++mt) {
        const int r0 = rowBase + wm + mt * 16 + og;
#pragma unroll
        for (int nt = 0; nt < 8; ++nt) {
            const int c0 = colBase + wn + nt * 8 + c * 2;
            float2 v0, v1;
            v0.x = C[mt][nt][0] * SCL; v0.y = C[mt][nt][1] * SCL;
            v1.x = C[mt][nt][2] * SCL; v1.y = C[mt][nt][3] * SCL;
            *reinterpret_cast<float2*>(&out[(size_t)r0 * ODIM + c0]) = v0;
            *reinterpret_cast<float2*>(&out[(size_t)(r0 + 8) * ODIM + c0]) = v1;
        }
    }
}

// ---------------- host ----------------
extern "C" void kernel_launch(void* const* d_in, const int* in_sizes, int n_in,
                              void* d_out, int out_size) {
    const float* x   = (const float*)d_in[0];   // [4096, 512]
    const float* var = (const float*)d_in[1];   // [4096, 64]
    const float* W   = (const float*)d_in[2];   // [64, 512, 512]
    const float* b1  = (const float*)d_in[3];   // [64, 512]
    float* out       = (float*)d_out;           // [4096, 512]

    {
        dim3 tb(32, 32), tg(IDIM / 32, NROWS / 32);
        transpose_x<<<tg, tb>>>(x);
    }

    cudaFuncSetAttribute(mlp_mma, cudaFuncAttributeMaxDynamicSharedMemorySize, SMEM_TOTAL);
    dim3 grid(ODIM / BN, NROWS / BM);   // (4, 32) = 128 CTAs = single wave
    mlp_mma<<<grid, NTH, SMEM_TOTAL>>>(var, W, b1, out);
}